// round 1
// baseline (speedup 1.0000x reference)
#include <cuda_runtime.h>

// PFNN: x[N,3] -> 4 parallel branches of (3->32 tanh, 32->32 tanh, 32->32 tanh, 32->1)
// out[N,4] fp32.
//
// Strategy: compute-bound kernel (620 flop/byte). Use sm_103a packed fp32 FMA
// (fma.rn.f32x2) to double FMA throughput vs scalar FFMA: each thread handles
// TWO points packed into the two f32 lanes of a 64-bit register. Weights are
// pre-splatted (w,w) in shared memory so the inner GEMV loop is
// LDS.128 (2 splatted weights) + 4 independent fma.rn.f32x2 chains.
// One branch per block (grid.y = 4) keeps static smem under 48KB and register
// pressure manageable. tanh via MUFU (tanh.approx.f32) - separate pipe from FMA.

#define HID 32
#define TPB 256
#define PPT 2          // points per thread (packed in f32x2)
#define NBRANCH 4

typedef unsigned long long u64;

__device__ __forceinline__ u64 fma2(u64 a, u64 b, u64 c) {
    u64 d;
    asm("fma.rn.f32x2 %0, %1, %2, %3;" : "=l"(d) : "l"(a), "l"(b), "l"(c));
    return d;
}

__device__ __forceinline__ u64 pack2(float lo, float hi) {
    u64 r;
    asm("mov.b64 %0, {%1, %2};" : "=l"(r) : "f"(lo), "f"(hi));
    return r;
}

__device__ __forceinline__ void unpack2(u64 v, float& lo, float& hi) {
    asm("mov.b64 {%0, %1}, %2;" : "=f"(lo), "=f"(hi) : "l"(v));
}

__device__ __forceinline__ float tanh_mufu(float x) {
    float y;
    asm("tanh.approx.f32 %0, %1;" : "=f"(y) : "f"(x));
    return y;
}

__device__ __forceinline__ u64 tanh2(u64 v) {
    float lo, hi;
    unpack2(v, lo, hi);
    return pack2(tanh_mufu(lo), tanh_mufu(hi));
}

// One hidden layer: hout = tanh(hin @ W + b), W splatted [k][j] in shared.
// 4 independent accumulator chains per j-group for ILP; weight loads are
// warp-uniform broadcasts (no bank conflicts), vectorized as ulonglong2 (LDS.128).
__device__ __forceinline__ void layer32(const u64* hin, u64* hout,
                                        const u64* __restrict__ sW,
                                        const u64* __restrict__ sB) {
#pragma unroll
    for (int j0 = 0; j0 < HID; j0 += 4) {
        u64 a0 = sB[j0], a1 = sB[j0 + 1], a2 = sB[j0 + 2], a3 = sB[j0 + 3];
#pragma unroll
        for (int k = 0; k < HID; k++) {
            const u64* row = &sW[k * HID + j0];
            ulonglong2 wA = *reinterpret_cast<const ulonglong2*>(row);
            ulonglong2 wB = *reinterpret_cast<const ulonglong2*>(row + 2);
            u64 hk = hin[k];
            a0 = fma2(hk, wA.x, a0);
            a1 = fma2(hk, wA.y, a1);
            a2 = fma2(hk, wB.x, a2);
            a3 = fma2(hk, wB.y, a3);
        }
        hout[j0]     = tanh2(a0);
        hout[j0 + 1] = tanh2(a1);
        hout[j0 + 2] = tanh2(a2);
        hout[j0 + 3] = tanh2(a3);
    }
}

__global__ __launch_bounds__(TPB, 1)
void pfnn_kernel(const float* __restrict__ x,
                 const float* __restrict__ W0, const float* __restrict__ b0,
                 const float* __restrict__ W1, const float* __restrict__ b1,
                 const float* __restrict__ W2, const float* __restrict__ b2,
                 const float* __restrict__ W3, const float* __restrict__ b3,
                 float* __restrict__ out, int N) {
    __shared__ u64 sW1[HID * HID];   // splatted (w,w), [k][j]
    __shared__ u64 sW2[HID * HID];
    __shared__ u64 sW0[3 * HID];     // [d][j]
    __shared__ u64 sB0[HID], sB1[HID], sB2[HID], sW3[HID];
    __shared__ float sB3;

    const int br = blockIdx.y;       // branch 0..3
    const int tid = threadIdx.x;

    // ---- stage weights (splatted) into shared ----
    for (int i = tid; i < HID * HID; i += TPB) {
        float w1 = W1[br * HID * HID + i];
        sW1[i] = pack2(w1, w1);
        float w2 = W2[br * HID * HID + i];
        sW2[i] = pack2(w2, w2);
    }
    if (tid < 3 * HID) {
        float w = W0[br * 3 * HID + tid];
        sW0[tid] = pack2(w, w);
    }
    if (tid < HID) {
        float v0 = b0[br * HID + tid]; sB0[tid] = pack2(v0, v0);
        float v1 = b1[br * HID + tid]; sB1[tid] = pack2(v1, v1);
        float v2 = b2[br * HID + tid]; sB2[tid] = pack2(v2, v2);
        float w3 = W3[br * HID + tid]; sW3[tid] = pack2(w3, w3);
    }
    if (tid == 0) sB3 = b3[br];
    __syncthreads();

    // ---- two points per thread ----
    const int n0 = blockIdx.x * (TPB * PPT) + tid;
    if (n0 >= N) return;
    const int n1 = n0 + TPB;
    const int n1c = (n1 < N) ? n1 : n0;   // clamp (duplicate work, store guarded)

    u64 xp0 = pack2(x[n0 * 3 + 0], x[n1c * 3 + 0]);
    u64 xp1 = pack2(x[n0 * 3 + 1], x[n1c * 3 + 1]);
    u64 xp2 = pack2(x[n0 * 3 + 2], x[n1c * 3 + 2]);

    u64 h[HID], g[HID];

    // layer 0: 3 -> 32
#pragma unroll
    for (int j = 0; j < HID; j++) {
        u64 a = sB0[j];
        a = fma2(xp0, sW0[j], a);
        a = fma2(xp1, sW0[HID + j], a);
        a = fma2(xp2, sW0[2 * HID + j], a);
        h[j] = tanh2(a);
    }

    // layers 1 and 2: 32 -> 32
    layer32(h, g, sW1, sB1);
    layer32(g, h, sW2, sB2);

    // layer 3: 32 -> 1
    u64 acc = pack2(sB3, sB3);
#pragma unroll
    for (int k = 0; k < HID; k++)
        acc = fma2(h[k], sW3[k], acc);

    float lo, hi;
    unpack2(acc, lo, hi);
    out[n0 * NBRANCH + br] = lo;
    if (n1 < N) out[n1 * NBRANCH + br] = hi;
}

extern "C" void kernel_launch(void* const* d_in, const int* in_sizes, int n_in,
                              void* d_out, int out_size) {
    const float* x  = (const float*)d_in[0];
    const float* W0 = (const float*)d_in[1];
    const float* b0 = (const float*)d_in[2];
    const float* W1 = (const float*)d_in[3];
    const float* b1 = (const float*)d_in[4];
    const float* W2 = (const float*)d_in[5];
    const float* b2 = (const float*)d_in[6];
    const float* W3 = (const float*)d_in[7];
    const float* b3 = (const float*)d_in[8];
    float* out = (float*)d_out;

    const int N = in_sizes[0] / 3;
    const int ptsPerBlock = TPB * PPT;
    dim3 grid((N + ptsPerBlock - 1) / ptsPerBlock, NBRANCH);
    pfnn_kernel<<<grid, TPB>>>(x, W0, b0, W1, b1, W2, b2, W3, b3, out, N);
}

// round 2
// speedup vs baseline: 1.4915x; 1.4915x over previous
#include <cuda_runtime.h>

// PFNN: x[N,3] -> 4 branches of (3->32 tanh, 32->32 tanh, 32->32 tanh, 32->1), out[N,4].
//
// R1 lesson: weight-splatted f32x2 made the smem pipe the binder (L1 90%, fma 43%).
// R2: pack OUTPUT NEURON PAIRS (j,j+1) in the f32x2 lanes instead of point pairs.
//  - weights stay in natural row-major f32 layout in shared: consecutive pairs ARE
//    the packed operand; one LDS.128 delivers 2 weight pairs (4 weights).
//  - activation h[k] is splatted in registers once per k (2 MOV on idle ALU pipe),
//    amortized over 16 j-pairs x 2 points = 32 fma2.
//  - 2 points per thread reuse each loaded weight twice more: 256 LDS.128 per
//    hidden layer vs 1024 fma2  ->  FMA pipe becomes the binder.

#define HID 32
#define TPB 256
#define NBRANCH 4

typedef unsigned long long u64;

__device__ __forceinline__ u64 fma2(u64 a, u64 b, u64 c) {
    u64 d;
    asm("fma.rn.f32x2 %0, %1, %2, %3;" : "=l"(d) : "l"(a), "l"(b), "l"(c));
    return d;
}

__device__ __forceinline__ u64 splat2(float v) {
    u64 r;
    asm("mov.b64 %0, {%1, %1};" : "=l"(r) : "f"(v));
    return r;
}

__device__ __forceinline__ void unpack2(u64 v, float& lo, float& hi) {
    asm("mov.b64 {%0, %1}, %2;" : "=f"(lo), "=f"(hi) : "l"(v));
}

__device__ __forceinline__ float tanh_mufu(float x) {
    float y;
    asm("tanh.approx.f32 %0, %1;" : "=f"(y) : "f"(x));
    return y;
}

// hout[p] = tanh(hin[p] @ W + b) for two points; W raw [k][j] f32 in shared,
// accumulators packed over (j, j+1) pairs.
__device__ __forceinline__ void layer32x2(const float* h0, const float* h1,
                                          float* o0, float* o1,
                                          const float* __restrict__ sW,
                                          const float* __restrict__ sB) {
    u64 acc0[HID / 2], acc1[HID / 2];
    const u64* bp = reinterpret_cast<const u64*>(sB);
#pragma unroll
    for (int j = 0; j < HID / 2; j++) { acc0[j] = bp[j]; acc1[j] = bp[j]; }

#pragma unroll
    for (int k = 0; k < HID; k++) {
        u64 a0 = splat2(h0[k]);
        u64 a1 = splat2(h1[k]);
        const ulonglong2* wr = reinterpret_cast<const ulonglong2*>(&sW[k * HID]);
#pragma unroll
        for (int g = 0; g < HID / 4; g++) {          // 8 x LDS.128 per k
            ulonglong2 w = wr[g];
            acc0[2 * g]     = fma2(a0, w.x, acc0[2 * g]);
            acc1[2 * g]     = fma2(a1, w.x, acc1[2 * g]);
            acc0[2 * g + 1] = fma2(a0, w.y, acc0[2 * g + 1]);
            acc1[2 * g + 1] = fma2(a1, w.y, acc1[2 * g + 1]);
        }
    }
#pragma unroll
    for (int j = 0; j < HID / 2; j++) {
        float a, b;
        unpack2(acc0[j], a, b);
        o0[2 * j] = tanh_mufu(a); o0[2 * j + 1] = tanh_mufu(b);
        unpack2(acc1[j], a, b);
        o1[2 * j] = tanh_mufu(a); o1[2 * j + 1] = tanh_mufu(b);
    }
}

__global__ __launch_bounds__(TPB, 1)
void pfnn_kernel(const float* __restrict__ x,
                 const float* __restrict__ W0, const float* __restrict__ b0,
                 const float* __restrict__ W1, const float* __restrict__ b1,
                 const float* __restrict__ W2, const float* __restrict__ b2,
                 const float* __restrict__ W3, const float* __restrict__ b3,
                 float* __restrict__ out, int N) {
    __shared__ __align__(16) float sW0[3 * HID];        // [d][j] raw
    __shared__ __align__(16) float sW1[HID * HID];      // [k][j] raw
    __shared__ __align__(16) float sW2[HID * HID];
    __shared__ __align__(16) float sB0[HID];
    __shared__ __align__(16) float sB1[HID];
    __shared__ __align__(16) float sB2[HID];
    __shared__ __align__(16) float sW3[HID];
    __shared__ float sB3;

    const int br = blockIdx.y;
    const int tid = threadIdx.x;

    // ---- stage raw weights into shared (vectorized) ----
    {
        const float4* w1 = reinterpret_cast<const float4*>(W1 + br * HID * HID);
        const float4* w2 = reinterpret_cast<const float4*>(W2 + br * HID * HID);
        float4* s1 = reinterpret_cast<float4*>(sW1);
        float4* s2 = reinterpret_cast<float4*>(sW2);
        for (int i = tid; i < HID * HID / 4; i += TPB) { s1[i] = w1[i]; s2[i] = w2[i]; }
    }
    if (tid < 3 * HID) sW0[tid] = W0[br * 3 * HID + tid];
    if (tid < HID) {
        sB0[tid] = b0[br * HID + tid];
        sB1[tid] = b1[br * HID + tid];
        sB2[tid] = b2[br * HID + tid];
        sW3[tid] = W3[br * HID + tid];
    }
    if (tid == 0) sB3 = b3[br];
    __syncthreads();

    // ---- two points per thread ----
    const int n0 = blockIdx.x * (TPB * 2) + tid;
    if (n0 >= N) return;
    const int n1 = n0 + TPB;
    const int n1c = (n1 < N) ? n1 : n0;

    float xa0 = x[n0 * 3 + 0], xa1 = x[n0 * 3 + 1], xa2 = x[n0 * 3 + 2];
    float xb0 = x[n1c * 3 + 0], xb1 = x[n1c * 3 + 1], xb2 = x[n1c * 3 + 2];

    float h0[HID], h1[HID], g0[HID], g1[HID];

    // layer 0: 3 -> 32
    {
        u64 acc0[HID / 2], acc1[HID / 2];
        const u64* bp = reinterpret_cast<const u64*>(sB0);
#pragma unroll
        for (int j = 0; j < HID / 2; j++) { acc0[j] = bp[j]; acc1[j] = bp[j]; }
        float xs0[3] = {xa0, xa1, xa2};
        float xs1[3] = {xb0, xb1, xb2};
#pragma unroll
        for (int d = 0; d < 3; d++) {
            u64 a0 = splat2(xs0[d]);
            u64 a1 = splat2(xs1[d]);
            const ulonglong2* wr = reinterpret_cast<const ulonglong2*>(&sW0[d * HID]);
#pragma unroll
            for (int g = 0; g < HID / 4; g++) {
                ulonglong2 w = wr[g];
                acc0[2 * g]     = fma2(a0, w.x, acc0[2 * g]);
                acc1[2 * g]     = fma2(a1, w.x, acc1[2 * g]);
                acc0[2 * g + 1] = fma2(a0, w.y, acc0[2 * g + 1]);
                acc1[2 * g + 1] = fma2(a1, w.y, acc1[2 * g + 1]);
            }
        }
#pragma unroll
        for (int j = 0; j < HID / 2; j++) {
            float a, b;
            unpack2(acc0[j], a, b);
            h0[2 * j] = tanh_mufu(a); h0[2 * j + 1] = tanh_mufu(b);
            unpack2(acc1[j], a, b);
            h1[2 * j] = tanh_mufu(a); h1[2 * j + 1] = tanh_mufu(b);
        }
    }

    // layers 1, 2
    layer32x2(h0, h1, g0, g1, sW1, sB1);
    layer32x2(g0, g1, h0, h1, sW2, sB2);

    // layer 3: 32 -> 1 (scalar, 4-way partial sums for ILP)
    float s0a = 0.f, s0b = 0.f, s0c = 0.f, s0d = 0.f;
    float s1a = 0.f, s1b = 0.f, s1c = 0.f, s1d = 0.f;
#pragma unroll
    for (int k = 0; k < HID; k += 4) {
        s0a = fmaf(h0[k],     sW3[k],     s0a);
        s0b = fmaf(h0[k + 1], sW3[k + 1], s0b);
        s0c = fmaf(h0[k + 2], sW3[k + 2], s0c);
        s0d = fmaf(h0[k + 3], sW3[k + 3], s0d);
        s1a = fmaf(h1[k],     sW3[k],     s1a);
        s1b = fmaf(h1[k + 1], sW3[k + 1], s1b);
        s1c = fmaf(h1[k + 2], sW3[k + 2], s1c);
        s1d = fmaf(h1[k + 3], sW3[k + 3], s1d);
    }
    out[n0 * NBRANCH + br] = sB3 + (s0a + s0b) + (s0c + s0d);
    if (n1 < N) out[n1 * NBRANCH + br] = sB3 + (s1a + s1b) + (s1c + s1d);
}

extern "C" void kernel_launch(void* const* d_in, const int* in_sizes, int n_in,
                              void* d_out, int out_size) {
    const float* x  = (const float*)d_in[0];
    const float* W0 = (const float*)d_in[1];
    const float* b0 = (const float*)d_in[2];
    const float* W1 = (const float*)d_in[3];
    const float* b1 = (const float*)d_in[4];
    const float* W2 = (const float*)d_in[5];
    const float* b2 = (const float*)d_in[6];
    const float* W3 = (const float*)d_in[7];
    const float* b3 = (const float*)d_in[8];
    float* out = (float*)d_out;

    const int N = in_sizes[0] / 3;
    const int ptsPerBlock = TPB * 2;
    dim3 grid((N + ptsPerBlock - 1) / ptsPerBlock, NBRANCH);
    pfnn_kernel<<<grid, TPB>>>(x, W0, b0, W1, b1, W2, b2, W3, b3, out, N);
}